// round 2
// baseline (speedup 1.0000x reference)
#include <cuda_runtime.h>
#include <cuda_bf16.h>
#include <cstdint>

// SINSentAddEmb: out[b,n,:] = LayerNorm(pe[n] + pe[para[b,n]] + pe[sent[b,n]]) * gamma + beta
// top_vecs (d_in[0]) is unused by the reference math — never read it (saves 134 MB HBM).
//
// Fixed problem shape: B=8, N=4096, H=1024, MAX_NSENT=5000, EPS=1e-12.
// sent_struct_vec is int32 on device (JAX downcasts the requested int64 with x64 off).

#define HDIM   1024
#define H4     (HDIM / 4)      // 256 float4 per row
#define NPOS   4096            // sequence length (power of two)
#define WPB    8               // warps per block
#define EPS_LN 1e-12f

__global__ void sinsent_addemb_ln_kernel(const int2*   __restrict__ ssv2,    // (B*N) int32 pairs (para, sent)
                                         const float4* __restrict__ pe4,     // (MAX_NSENT, H/4)
                                         const float4* __restrict__ gamma4,  // (H/4)
                                         const float4* __restrict__ beta4,   // (H/4)
                                         float4*       __restrict__ out4,    // (B*N, H/4)
                                         int rows)
{
    const int warp_in_blk = threadIdx.x >> 5;
    const int lane        = threadIdx.x & 31;
    const int row         = blockIdx.x * WPB + warp_in_blk;
    if (row >= rows) return;

    const int n = row & (NPOS - 1);           // position within sequence

    // Both int32 indices in one 8B load; uniform address within warp -> 1 transaction + broadcast.
    const int2 idx = ssv2[row];

    const float4* __restrict__ pn = pe4 + (size_t)n     * H4;
    const float4* __restrict__ pp = pe4 + (size_t)idx.x * H4;
    const float4* __restrict__ ps = pe4 + (size_t)idx.y * H4;

    // Gather + sum: 32 floats per lane, held in registers.
    float4 e[8];
    float s = 0.0f, sq = 0.0f;
#pragma unroll
    for (int i = 0; i < 8; i++) {
        const int j = i * 32 + lane;          // coalesced: 32 lanes x 16B = 512B per stream
        const float4 a = pn[j];
        const float4 b = pp[j];
        const float4 c = ps[j];
        float4 v;
        v.x = a.x + b.x + c.x;
        v.y = a.y + b.y + c.y;
        v.z = a.z + b.z + c.z;
        v.w = a.w + b.w + c.w;
        e[i] = v;
        s  += v.x + v.y + v.z + v.w;
        sq += v.x * v.x + v.y * v.y + v.z * v.z + v.w * v.w;
    }

    // Warp-wide butterfly reduction of (sum, sumsq).
#pragma unroll
    for (int o = 16; o > 0; o >>= 1) {
        s  += __shfl_xor_sync(0xffffffffu, s,  o);
        sq += __shfl_xor_sync(0xffffffffu, sq, o);
    }

    const float mean = s  * (1.0f / HDIM);
    const float var  = sq * (1.0f / HDIM) - mean * mean;
    const float rstd = rsqrtf(var + EPS_LN);

    float4* __restrict__ orow = out4 + (size_t)row * H4;
#pragma unroll
    for (int i = 0; i < 8; i++) {
        const int j = i * 32 + lane;
        const float4 g  = gamma4[j];          // hot in L1/L2 (8 KB total)
        const float4 bt = beta4[j];
        const float4 v  = e[i];
        float4 o;
        o.x = (v.x - mean) * rstd * g.x + bt.x;
        o.y = (v.y - mean) * rstd * g.y + bt.y;
        o.z = (v.z - mean) * rstd * g.z + bt.z;
        o.w = (v.w - mean) * rstd * g.w + bt.w;
        orow[j] = o;                          // STG.128, fully coalesced
    }
}

extern "C" void kernel_launch(void* const* d_in, const int* in_sizes, int n_in,
                              void* d_out, int out_size)
{
    // metadata order: [0] top_vecs f32 (UNUSED), [1] sent_struct_vec int32,
    //                 [2] pe f32, [3] gamma f32, [4] beta f32
    const int2*   ssv2   = (const int2*)d_in[1];
    const float4* pe4    = (const float4*)d_in[2];
    const float4* gamma4 = (const float4*)d_in[3];
    const float4* beta4  = (const float4*)d_in[4];
    float4*       out4   = (float4*)d_out;

    const int rows = in_sizes[1] / 2;         // B*N = 32768

    const int threads = WPB * 32;             // 256
    const int blocks  = (rows + WPB - 1) / WPB;
    sinsent_addemb_ln_kernel<<<blocks, threads>>>(ssv2, pe4, gamma4, beta4, out4, rows);
}